// round 14
// baseline (speedup 1.0000x reference)
#include <cuda_runtime.h>
#include <cuda_bf16.h>
#include <math.h>
#include <stdint.h>

#define NN 50000
#define NE 800000
#define HID 128
#define OUTC 40

// ---------------- scratch (no allocation allowed; 256B-aligned for vector access) ----------------
__device__ __align__(256) float g_h[(size_t)NN * HID];
__device__ __align__(256) float g_hnew[(size_t)NN * HID];
__device__ __align__(256) float g_agg[(size_t)NN * HID];
__device__ __align__(256) float g_Wc[3 * 3 * HID * HID];        // per-layer combined W @ W_ih^T (fp32)
__device__ __align__(256) uint32_t g_Wtf[3 * 6 * HID * HID];    // tf32, k-permuted: [L][gate][n][kperm]

// ---------------- helpers ----------------
__device__ __forceinline__ uint32_t f2tf(float f)
{
    uint32_t r;
    asm("cvt.rna.tf32.f32 %0, %1;" : "=r"(r) : "f"(f));
    return r;
}

__device__ __forceinline__ void mma_tf32(float c[4],
    uint32_t a0, uint32_t a1, uint32_t a2, uint32_t a3,
    uint32_t b0, uint32_t b1)
{
    asm("mma.sync.aligned.m16n8k8.row.col.f32.tf32.tf32.f32 "
        "{%0,%1,%2,%3}, {%4,%5,%6,%7}, {%8,%9}, {%0,%1,%2,%3};"
        : "+f"(c[0]), "+f"(c[1]), "+f"(c[2]), "+f"(c[3])
        : "r"(a0), "r"(a1), "r"(a2), "r"(a3), "r"(b0), "r"(b1));
}

__device__ __forceinline__ float sigmoidf_(float x) { return 1.f / (1.f + expf(-x)); }

// ---------------- combine: Wc_L[j][k'] = sum_c layer_W[L][k'][c] * W_ih[j][c] ----------------
// grid (12, 4, 3), block 256. SCALAR smem ops only.
__global__ __launch_bounds__(256) void combine_kernel(
    const float* __restrict__ layer_W, const float* __restrict__ W_ih,
    float* __restrict__ Wc)
{
    __shared__ float sWih[32][132];
    __shared__ float sW[32][132];

    const int L   = blockIdx.z;
    const int j0  = blockIdx.x * 32;
    const int kp0 = blockIdx.y * 32;
    const float* Wl = layer_W + (size_t)L * HID * HID;

    for (int i = threadIdx.x; i < 32 * 128; i += 256) {
        int row = i >> 7;
        int cc  = i & 127;
        sWih[row][cc] = W_ih[(size_t)(j0 + row) * HID + cc];
        sW[row][cc]   = Wl[(size_t)(kp0 + row) * HID + cc];
    }
    __syncthreads();

    const int j  = threadIdx.x & 31;
    const int kp = (threadIdx.x >> 5) * 4;
    float acc[4] = {0.f, 0.f, 0.f, 0.f};
#pragma unroll 4
    for (int c = 0; c < 128; c++) {
        float wij = sWih[j][c];
        acc[0] += wij * sW[kp + 0][c];
        acc[1] += wij * sW[kp + 1][c];
        acc[2] += wij * sW[kp + 2][c];
        acc[3] += wij * sW[kp + 3][c];
    }
    float* outp = Wc + (size_t)L * 3 * HID * HID + (size_t)(j0 + j) * HID + kp0 + kp;
    outp[0] = acc[0]; outp[1] = acc[1]; outp[2] = acc[2]; outp[3] = acc[3];
}

// ---------------- pack GRU weights to tf32 in k-permuted layout ----------------
// Row = (L, gate, n): gates 0-2 from Wc_L, gates 3-5 from W_hh.
// Dest position t holds source k = (t & ~7) + ((t&7)>>1) + 4*(t&1)   (inverse of phys perm).
__global__ __launch_bounds__(128) void pack_weights_kernel(
    const float* __restrict__ Wc, const float* __restrict__ W_hh,
    uint32_t* __restrict__ wtf)
{
    const int bid = blockIdx.x;
    const int L   = bid / 768;
    const int rem = bid % 768;
    const int g   = rem / 128;
    const int n   = rem % 128;

    const float* src = (g < 3)
        ? Wc + (size_t)L * 3 * HID * HID + (size_t)(g * HID + n) * HID
        : W_hh + (size_t)((g - 3) * HID + n) * HID;

    const int t = threadIdx.x;                           // 0..127 dest (perm) position
    const int p = t & 7;
    const int src_k = (t & ~7) + (p >> 1) + 4 * (p & 1); // inverse perm
    wtf[(size_t)bid * HID + t] = f2tf(src[src_k]);
}

// ---------------- C[M,128] = A[M,128] @ W[128,128] (+bias), tf32 MMA ----------------
__global__ __launch_bounds__(256, 2) void gemm_tf32_kernel(
    const float* __restrict__ A, const float* __restrict__ W,
    const float* __restrict__ bias, float* __restrict__ C)
{
    __shared__ uint32_t sA[64][36];
    __shared__ uint32_t sB[128][36];

    const int tid  = threadIdx.x;
    const int lane = tid & 31;
    const int warp = tid >> 5;
    const int wm   = warp & 3;
    const int wn   = warp >> 2;
    const int ty   = lane >> 2;
    const int tx   = lane & 3;
    const int row0 = blockIdx.x * 64;

    float c[8][4];
#pragma unroll
    for (int t = 0; t < 8; t++)
#pragma unroll
        for (int i = 0; i < 4; i++) c[t][i] = 0.f;

    for (int kc = 0; kc < 128; kc += 32) {
#pragma unroll
        for (int r = 0; r < 2; r++) {
            int id  = tid + r * 256;
            int row = id >> 3;
            int k4  = id & 7;
            int rr  = row0 + row; if (rr >= NN) rr = NN - 1;
            float4 v = *(const float4*)(A + (size_t)rr * HID + kc + k4 * 4);
            int base = (k4 >> 1) * 8 + (k4 & 1);
            sA[row][base + 0] = f2tf(v.x);
            sA[row][base + 2] = f2tf(v.y);
            sA[row][base + 4] = f2tf(v.z);
            sA[row][base + 6] = f2tf(v.w);
        }
#pragma unroll
        for (int r = 0; r < 4; r++) {
            int id = tid + r * 256;
            int kk = id & 31;
            int nq = id >> 5;
            float4 v = *(const float4*)(W + (size_t)(kc + kk) * HID + nq * 4);
            int k8   = (kk >> 3) * 8;
            int phys = k8 + 2 * ((kk & 7) & 3) + ((kk & 7) >> 2);
            sB[nq * 4 + 0][phys] = f2tf(v.x);
            sB[nq * 4 + 1][phys] = f2tf(v.y);
            sB[nq * 4 + 2][phys] = f2tf(v.z);
            sB[nq * 4 + 3][phys] = f2tf(v.w);
        }
        __syncthreads();

#pragma unroll
        for (int k8 = 0; k8 < 32; k8 += 8) {
            uint2 a02 = *(const uint2*)&sA[wm * 16 + ty][k8 + 2 * tx];
            uint2 a13 = *(const uint2*)&sA[wm * 16 + ty + 8][k8 + 2 * tx];
#pragma unroll
            for (int t = 0; t < 8; t++) {
                int n = wn * 64 + t * 8 + ty;
                uint2 b = *(const uint2*)&sB[n][k8 + 2 * tx];
                mma_tf32(c[t], a02.x, a13.x, a02.y, a13.y, b.x, b.y);
            }
        }
        __syncthreads();
    }

    const int r0 = row0 + wm * 16 + ty;
    const int r1 = r0 + 8;
#pragma unroll
    for (int t = 0; t < 8; t++) {
        int col = wn * 64 + t * 8 + 2 * tx;
        float b0 = bias ? bias[col]     : 0.f;
        float b1 = bias ? bias[col + 1] : 0.f;
        if (r0 < NN)
            *(float2*)&C[(size_t)r0 * HID + col] = make_float2(c[t][0] + b0, c[t][1] + b1);
        if (r1 < NN)
            *(float2*)&C[(size_t)r1 * HID + col] = make_float2(c[t][2] + b0, c[t][3] + b1);
    }
}

// ---------------- zero agg ----------------
__global__ void zero_kernel(float4* __restrict__ p, int n4)
{
    int i = blockIdx.x * blockDim.x + threadIdx.x;
    if (i < n4) p[i] = make_float4(0.f, 0.f, 0.f, 0.f);
}

// ---------------- scatter-add h over edges (warp per edge, v4 RED) ----------------
__global__ __launch_bounds__(256) void scatter_kernel(
    const int* __restrict__ ei, const float* __restrict__ h, float* __restrict__ agg)
{
    const int e = blockIdx.x * 8 + (threadIdx.x >> 5);
    const int lane = threadIdx.x & 31;
    const int src = __ldg(ei + e);
    const int dst = __ldg(ei + NE + e);
    float4 v = *(const float4*)(h + (size_t)src * HID + lane * 4);
    float* p = agg + (size_t)dst * HID + lane * 4;
    asm volatile("red.global.add.v4.f32 [%0], {%1,%2,%3,%4};"
                 :: "l"(p), "f"(v.x), "f"(v.y), "f"(v.z), "f"(v.w) : "memory");
}

// ---------------- fused GRU with tf32 MMA (pre-packed weights, dynamic smem) ----------------
// grid (ceil(NN/64), 2). Block 512 = 16 warps: 4 M x 4 N. Tile m64 x n64, warp m16 x n16.
// Dynamic smem layout (uint32 words): sAg[64][36] | sH[64][36] | sW[6][64][36]  = 73728 bytes.
#define GRU_SMEM_BYTES ((64 * 36 + 64 * 36 + 6 * 64 * 36) * 4)

__global__ __launch_bounds__(512, 1) void gru_tf32_kernel(
    const float* __restrict__ agg, const float* __restrict__ h,
    const uint32_t* __restrict__ wtf,   // [6][128][128] tf32, k-permuted, this layer
    const float* __restrict__ b_ih, const float* __restrict__ b_hh,
    float* __restrict__ hnew)
{
    extern __shared__ uint32_t smem[];
    uint32_t (*sAg)[36] = (uint32_t(*)[36])smem;                 // [64][36]
    uint32_t (*sH)[36]  = (uint32_t(*)[36])(smem + 64 * 36);     // [64][36]
    uint32_t (*sW)[36]  = (uint32_t(*)[36])(smem + 2 * 64 * 36); // [6*64][36]

    const int tid   = threadIdx.x;
    const int lane  = tid & 31;
    const int warp  = tid >> 5;       // 0..15
    const int wm    = warp & 3;
    const int wn    = warp >> 2;      // 0..3
    const int ty    = lane >> 2;
    const int tx    = lane & 3;
    const int node0 = blockIdx.x * 64;
    const int colB  = blockIdx.y * 64;

    float c[6][2][4];
#pragma unroll
    for (int g = 0; g < 6; g++)
#pragma unroll
        for (int t = 0; t < 2; t++)
#pragma unroll
            for (int i = 0; i < 4; i++) c[g][t][i] = 0.f;

    for (int kc = 0; kc < 128; kc += 32) {
        // agg/h tiles: 64 rows x 32 k = 512 f4 each; 1 per thread per array
        {
            int row = tid >> 3;            // 0..63
            int k4  = tid & 7;
            int rr  = node0 + row; if (rr >= NN) rr = NN - 1;
            float4 va = *(const float4*)(agg + (size_t)rr * HID + kc + k4 * 4);
            float4 vh = *(const float4*)(h   + (size_t)rr * HID + kc + k4 * 4);
            int base = (k4 >> 1) * 8 + (k4 & 1);
            sAg[row][base + 0] = f2tf(va.x);
            sAg[row][base + 2] = f2tf(va.y);
            sAg[row][base + 4] = f2tf(va.z);
            sAg[row][base + 6] = f2tf(va.w);
            sH[row][base + 0] = f2tf(vh.x);
            sH[row][base + 2] = f2tf(vh.y);
            sH[row][base + 4] = f2tf(vh.z);
            sH[row][base + 6] = f2tf(vh.w);
        }
        // weights: 6 gates x 64 n x 8 uint4 = 3072 uint4; 6 per thread; direct copy (pre-converted)
#pragma unroll
        for (int r = 0; r < 6; r++) {
            int id  = tid + r * 512;       // 0..3071
            int g   = id >> 9;             // 0..5
            int rem = id & 511;
            int n   = rem >> 3;            // 0..63
            int k4  = rem & 7;
            uint4 w = *(const uint4*)(wtf + ((size_t)(g * HID + colB + n)) * HID + kc + k4 * 4);
            *(uint4*)&sW[g * 64 + n][k4 * 4] = w;
        }
        __syncthreads();

#pragma unroll
        for (int k8 = 0; k8 < 32; k8 += 8) {
            uint2 ag02 = *(const uint2*)&sAg[wm * 16 + ty][k8 + 2 * tx];
            uint2 ag13 = *(const uint2*)&sAg[wm * 16 + ty + 8][k8 + 2 * tx];
            uint2 h02  = *(const uint2*)&sH[wm * 16 + ty][k8 + 2 * tx];
            uint2 h13  = *(const uint2*)&sH[wm * 16 + ty + 8][k8 + 2 * tx];
#pragma unroll
            for (int t = 0; t < 2; t++) {
                int n = wn * 16 + t * 8 + ty;
#pragma unroll
                for (int g = 0; g < 3; g++) {
                    uint2 b = *(const uint2*)&sW[g * 64 + n][k8 + 2 * tx];
                    mma_tf32(c[g][t], ag02.x, ag13.x, ag02.y, ag13.y, b.x, b.y);
                }
#pragma unroll
                for (int g = 3; g < 6; g++) {
                    uint2 b = *(const uint2*)&sW[g * 64 + n][k8 + 2 * tx];
                    mma_tf32(c[g][t], h02.x, h13.x, h02.y, h13.y, b.x, b.y);
                }
            }
        }
        __syncthreads();
    }

    const int r0 = node0 + wm * 16 + ty;
    const int r1 = r0 + 8;
#pragma unroll
    for (int t = 0; t < 2; t++) {
        int j = colB + wn * 16 + t * 8 + 2 * tx;
        float bir0 = b_ih[j],           bir1 = b_ih[j + 1];
        float biz0 = b_ih[HID + j],     biz1 = b_ih[HID + j + 1];
        float bin0 = b_ih[2 * HID + j], bin1 = b_ih[2 * HID + j + 1];
        float bhr0 = b_hh[j],           bhr1 = b_hh[j + 1];
        float bhz0 = b_hh[HID + j],     bhz1 = b_hh[HID + j + 1];
        float bhn0 = b_hh[2 * HID + j], bhn1 = b_hh[2 * HID + j + 1];

        if (r0 < NN) {
            float2 hp = *(const float2*)(h + (size_t)r0 * HID + j);
            float rr0 = sigmoidf_(c[0][t][0] + bir0 + c[3][t][0] + bhr0);
            float zz0 = sigmoidf_(c[1][t][0] + biz0 + c[4][t][0] + bhz0);
            float nn0 = tanhf(c[2][t][0] + bin0 + rr0 * (c[5][t][0] + bhn0));
            float rr1 = sigmoidf_(c[0][t][1] + bir1 + c[3][t][1] + bhr1);
            float zz1 = sigmoidf_(c[1][t][1] + biz1 + c[4][t][1] + bhz1);
            float nn1 = tanhf(c[2][t][1] + bin1 + rr1 * (c[5][t][1] + bhn1));
            *(float2*)&hnew[(size_t)r0 * HID + j] =
                make_float2((1.f - zz0) * nn0 + zz0 * hp.x,
                            (1.f - zz1) * nn1 + zz1 * hp.y);
        }
        if (r1 < NN) {
            float2 hp = *(const float2*)(h + (size_t)r1 * HID + j);
            float rr0 = sigmoidf_(c[0][t][2] + bir0 + c[3][t][2] + bhr0);
            float zz0 = sigmoidf_(c[1][t][2] + biz0 + c[4][t][2] + bhz0);
            float nn0 = tanhf(c[2][t][2] + bin0 + rr0 * (c[5][t][2] + bhn0));
            float rr1 = sigmoidf_(c[0][t][3] + bir1 + c[3][t][3] + bhr1);
            float zz1 = sigmoidf_(c[1][t][3] + biz1 + c[4][t][3] + bhz1);
            float nn1 = tanhf(c[2][t][3] + bin1 + rr1 * (c[5][t][3] + bhn1));
            *(float2*)&hnew[(size_t)r1 * HID + j] =
                make_float2((1.f - zz0) * nn0 + zz0 * hp.x,
                            (1.f - zz1) * nn1 + zz1 * hp.y);
        }
    }
}

// ---------------- relu -> out proj (128->40) -> log_softmax ----------------
__global__ __launch_bounds__(128) void out_kernel(
    const float* __restrict__ h, const float* __restrict__ W_out,
    const float* __restrict__ b_out, float* __restrict__ out)
{
    __shared__ float sW[128][48];
    __shared__ float sB[48];
    __shared__ float sH[4][128];

    const int tid = threadIdx.x;
    for (int i = tid; i < 128 * 48; i += 128) {
        int k = i / 48, cc = i % 48;
        sW[k][cc] = (cc < OUTC) ? W_out[(size_t)k * OUTC + cc] : 0.f;
    }
    if (tid < 48) sB[tid] = (tid < OUTC) ? b_out[tid] : 0.f;

    const int w = tid >> 5, lane = tid & 31;
    const int node = blockIdx.x * 4 + w;
    float4 hv = *(const float4*)(h + (size_t)node * HID + lane * 4);
    hv.x = fmaxf(hv.x, 0.f); hv.y = fmaxf(hv.y, 0.f);
    hv.z = fmaxf(hv.z, 0.f); hv.w = fmaxf(hv.w, 0.f);
    *(float4*)&sH[w][lane * 4] = hv;
    __syncthreads();

    const int c1 = 32 + (lane & 7);
    float acc0 = 0.f, acc1 = 0.f;
#pragma unroll 4
    for (int k = 0; k < 128; k++) {
        float a = sH[w][k];
        acc0 += a * sW[k][lane];
        acc1 += a * sW[k][c1];
    }
    float v0 = acc0 + sB[lane];
    float v1 = acc1 + sB[c1];
    const bool has1 = lane < 8;

    float mx = fmaxf(v0, has1 ? v1 : -INFINITY);
#pragma unroll
    for (int o = 16; o > 0; o >>= 1) mx = fmaxf(mx, __shfl_xor_sync(0xFFFFFFFFu, mx, o));
    float s = expf(v0 - mx) + (has1 ? expf(v1 - mx) : 0.f);
#pragma unroll
    for (int o = 16; o > 0; o >>= 1) s += __shfl_xor_sync(0xFFFFFFFFu, s, o);
    float lse = mx + logf(s);

    out[(size_t)node * OUTC + lane] = v0 - lse;
    if (has1) out[(size_t)node * OUTC + 32 + lane] = v1 - lse;
}

// ---------------- launch ----------------
extern "C" void kernel_launch(void* const* d_in, const int* in_sizes, int n_in,
                              void* d_out, int out_size)
{
    const float* x       = (const float*)d_in[0];
    const int*   ei      = (const int*)  d_in[1];
    const float* W_in    = (const float*)d_in[2];
    const float* b_in    = (const float*)d_in[3];
    const float* layer_W = (const float*)d_in[4];
    const float* W_ih    = (const float*)d_in[5];
    const float* W_hh    = (const float*)d_in[6];
    const float* b_ih    = (const float*)d_in[7];
    const float* b_hh    = (const float*)d_in[8];
    const float* W_out   = (const float*)d_in[9];
    const float* b_out   = (const float*)d_in[10];

    float *hbuf, *aggbuf, *hnewbuf, *wcbuf;
    uint32_t* wtfbuf;
    cudaGetSymbolAddress((void**)&hbuf,    g_h);
    cudaGetSymbolAddress((void**)&aggbuf,  g_agg);
    cudaGetSymbolAddress((void**)&hnewbuf, g_hnew);
    cudaGetSymbolAddress((void**)&wcbuf,   g_Wc);
    cudaGetSymbolAddress((void**)&wtfbuf,  g_Wtf);

    // opt-in to >48KB dynamic smem for the GRU kernel (host-side, immediate; capture-legal)
    cudaFuncSetAttribute(gru_tf32_kernel,
                         cudaFuncAttributeMaxDynamicSharedMemorySize, GRU_SMEM_BYTES);

    const int mmBlocks = (NN + 63) / 64;   // 782
    const int n4 = NN * HID / 4;           // 1.6M

    // precompute combined message+input-gate weights, then tf32-pack all GRU weights
    combine_kernel<<<dim3(12, 4, 3), 256>>>(layer_W, W_ih, wcbuf);
    pack_weights_kernel<<<3 * 6 * HID, 128>>>(wcbuf, W_hh, wtfbuf);

    gemm_tf32_kernel<<<mmBlocks, 256>>>(x, W_in, b_in, hbuf);

    float* hcur = hbuf;
    float* hnext = hnewbuf;
    for (int L = 0; L < 3; L++) {
        zero_kernel<<<(n4 + 255) / 256, 256>>>((float4*)aggbuf, n4);
        scatter_kernel<<<NE / 8, 256>>>(ei, hcur, aggbuf);
        gru_tf32_kernel<<<dim3(mmBlocks, 2), 512, GRU_SMEM_BYTES>>>(
            aggbuf, hcur, wtfbuf + (size_t)L * 6 * HID * HID, b_ih, b_hh, hnext);
        float* t = hcur; hcur = hnext; hnext = t;
    }

    out_kernel<<<NN / 4, 128>>>(hcur, W_out, b_out, (float*)d_out);
}

// round 15
// speedup vs baseline: 1.0220x; 1.0220x over previous
#include <cuda_runtime.h>
#include <cuda_bf16.h>
#include <math.h>
#include <stdint.h>

#define NN 50000
#define NE 800000
#define HID 128
#define OUTC 40

// ---------------- scratch (no allocation allowed; 256B-aligned for vector access) ----------------
__device__ __align__(256) float g_h[(size_t)NN * HID];
__device__ __align__(256) float g_hnew[(size_t)NN * HID];
__device__ __align__(256) float g_agg[(size_t)NN * HID];
__device__ __align__(256) float g_Wc[3 * 3 * HID * HID];        // per-layer combined W @ W_ih^T (fp32)
__device__ __align__(256) uint32_t g_Wtf[3 * 6 * HID * HID];    // tf32, k-permuted: [L][gate][n][kperm]

// ---------------- helpers ----------------
__device__ __forceinline__ uint32_t f2tf(float f)
{
    uint32_t r;
    asm("cvt.rna.tf32.f32 %0, %1;" : "=r"(r) : "f"(f));
    return r;
}

__device__ __forceinline__ void mma_tf32(float c[4],
    uint32_t a0, uint32_t a1, uint32_t a2, uint32_t a3,
    uint32_t b0, uint32_t b1)
{
    asm("mma.sync.aligned.m16n8k8.row.col.f32.tf32.tf32.f32 "
        "{%0,%1,%2,%3}, {%4,%5,%6,%7}, {%8,%9}, {%0,%1,%2,%3};"
        : "+f"(c[0]), "+f"(c[1]), "+f"(c[2]), "+f"(c[3])
        : "r"(a0), "r"(a1), "r"(a2), "r"(a3), "r"(b0), "r"(b1));
}

__device__ __forceinline__ void cp_async16(void* smem_dst, const void* gmem_src)
{
    unsigned sa = (unsigned)__cvta_generic_to_shared(smem_dst);
    asm volatile("cp.async.cg.shared.global [%0], [%1], 16;" :: "r"(sa), "l"(gmem_src));
}
__device__ __forceinline__ void cp_async_commit() { asm volatile("cp.async.commit_group;"); }
__device__ __forceinline__ void cp_async_wait0()  { asm volatile("cp.async.wait_group 0;"); }

__device__ __forceinline__ float sigmoidf_(float x) { return 1.f / (1.f + expf(-x)); }

// ---------------- combine: Wc_L[j][k'] = sum_c layer_W[L][k'][c] * W_ih[j][c] ----------------
__global__ __launch_bounds__(256) void combine_kernel(
    const float* __restrict__ layer_W, const float* __restrict__ W_ih,
    float* __restrict__ Wc)
{
    __shared__ float sWih[32][132];
    __shared__ float sW[32][132];

    const int L   = blockIdx.z;
    const int j0  = blockIdx.x * 32;
    const int kp0 = blockIdx.y * 32;
    const float* Wl = layer_W + (size_t)L * HID * HID;

    for (int i = threadIdx.x; i < 32 * 128; i += 256) {
        int row = i >> 7;
        int cc  = i & 127;
        sWih[row][cc] = W_ih[(size_t)(j0 + row) * HID + cc];
        sW[row][cc]   = Wl[(size_t)(kp0 + row) * HID + cc];
    }
    __syncthreads();

    const int j  = threadIdx.x & 31;
    const int kp = (threadIdx.x >> 5) * 4;
    float acc[4] = {0.f, 0.f, 0.f, 0.f};
#pragma unroll 4
    for (int c = 0; c < 128; c++) {
        float wij = sWih[j][c];
        acc[0] += wij * sW[kp + 0][c];
        acc[1] += wij * sW[kp + 1][c];
        acc[2] += wij * sW[kp + 2][c];
        acc[3] += wij * sW[kp + 3][c];
    }
    float* outp = Wc + (size_t)L * 3 * HID * HID + (size_t)(j0 + j) * HID + kp0 + kp;
    outp[0] = acc[0]; outp[1] = acc[1]; outp[2] = acc[2]; outp[3] = acc[3];
}

// ---------------- pack GRU weights to tf32 in k-permuted layout ----------------
__global__ __launch_bounds__(128) void pack_weights_kernel(
    const float* __restrict__ Wc, const float* __restrict__ W_hh,
    uint32_t* __restrict__ wtf)
{
    const int bid = blockIdx.x;
    const int L   = bid / 768;
    const int rem = bid % 768;
    const int g   = rem / 128;
    const int n   = rem % 128;

    const float* src = (g < 3)
        ? Wc + (size_t)L * 3 * HID * HID + (size_t)(g * HID + n) * HID
        : W_hh + (size_t)((g - 3) * HID + n) * HID;

    const int t = threadIdx.x;
    const int p = t & 7;
    const int src_k = (t & ~7) + (p >> 1) + 4 * (p & 1);
    wtf[(size_t)bid * HID + t] = f2tf(src[src_k]);
}

// ---------------- C[M,128] = A[M,128] @ W[128,128] (+bias), tf32 MMA ----------------
__global__ __launch_bounds__(256, 2) void gemm_tf32_kernel(
    const float* __restrict__ A, const float* __restrict__ W,
    const float* __restrict__ bias, float* __restrict__ C)
{
    __shared__ uint32_t sA[64][36];
    __shared__ uint32_t sB[128][36];

    const int tid  = threadIdx.x;
    const int lane = tid & 31;
    const int warp = tid >> 5;
    const int wm   = warp & 3;
    const int wn   = warp >> 2;
    const int ty   = lane >> 2;
    const int tx   = lane & 3;
    const int row0 = blockIdx.x * 64;

    float c[8][4];
#pragma unroll
    for (int t = 0; t < 8; t++)
#pragma unroll
        for (int i = 0; i < 4; i++) c[t][i] = 0.f;

    for (int kc = 0; kc < 128; kc += 32) {
#pragma unroll
        for (int r = 0; r < 2; r++) {
            int id  = tid + r * 256;
            int row = id >> 3;
            int k4  = id & 7;
            int rr  = row0 + row; if (rr >= NN) rr = NN - 1;
            float4 v = *(const float4*)(A + (size_t)rr * HID + kc + k4 * 4);
            int base = (k4 >> 1) * 8 + (k4 & 1);
            sA[row][base + 0] = f2tf(v.x);
            sA[row][base + 2] = f2tf(v.y);
            sA[row][base + 4] = f2tf(v.z);
            sA[row][base + 6] = f2tf(v.w);
        }
#pragma unroll
        for (int r = 0; r < 4; r++) {
            int id = tid + r * 256;
            int kk = id & 31;
            int nq = id >> 5;
            float4 v = *(const float4*)(W + (size_t)(kc + kk) * HID + nq * 4);
            int k8   = (kk >> 3) * 8;
            int phys = k8 + 2 * ((kk & 7) & 3) + ((kk & 7) >> 2);
            sB[nq * 4 + 0][phys] = f2tf(v.x);
            sB[nq * 4 + 1][phys] = f2tf(v.y);
            sB[nq * 4 + 2][phys] = f2tf(v.z);
            sB[nq * 4 + 3][phys] = f2tf(v.w);
        }
        __syncthreads();

#pragma unroll
        for (int k8 = 0; k8 < 32; k8 += 8) {
            uint2 a02 = *(const uint2*)&sA[wm * 16 + ty][k8 + 2 * tx];
            uint2 a13 = *(const uint2*)&sA[wm * 16 + ty + 8][k8 + 2 * tx];
#pragma unroll
            for (int t = 0; t < 8; t++) {
                int n = wn * 64 + t * 8 + ty;
                uint2 b = *(const uint2*)&sB[n][k8 + 2 * tx];
                mma_tf32(c[t], a02.x, a13.x, a02.y, a13.y, b.x, b.y);
            }
        }
        __syncthreads();
    }

    const int r0 = row0 + wm * 16 + ty;
    const int r1 = r0 + 8;
#pragma unroll
    for (int t = 0; t < 8; t++) {
        int col = wn * 64 + t * 8 + 2 * tx;
        float b0 = bias ? bias[col]     : 0.f;
        float b1 = bias ? bias[col + 1] : 0.f;
        if (r0 < NN)
            *(float2*)&C[(size_t)r0 * HID + col] = make_float2(c[t][0] + b0, c[t][1] + b1);
        if (r1 < NN)
            *(float2*)&C[(size_t)r1 * HID + col] = make_float2(c[t][2] + b0, c[t][3] + b1);
    }
}

// ---------------- zero agg ----------------
__global__ void zero_kernel(float4* __restrict__ p, int n4)
{
    int i = blockIdx.x * blockDim.x + threadIdx.x;
    if (i < n4) p[i] = make_float4(0.f, 0.f, 0.f, 0.f);
}

// ---------------- scatter-add h over edges (warp per edge, v4 RED) ----------------
__global__ __launch_bounds__(256) void scatter_kernel(
    const int* __restrict__ ei, const float* __restrict__ h, float* __restrict__ agg)
{
    const int e = blockIdx.x * 8 + (threadIdx.x >> 5);
    const int lane = threadIdx.x & 31;
    const int src = __ldg(ei + e);
    const int dst = __ldg(ei + NE + e);
    float4 v = *(const float4*)(h + (size_t)src * HID + lane * 4);
    float* p = agg + (size_t)dst * HID + lane * 4;
    asm volatile("red.global.add.v4.f32 [%0], {%1,%2,%3,%4};"
                 :: "l"(p), "f"(v.x), "f"(v.y), "f"(v.z), "f"(v.w) : "memory");
}

// ---------------- pipelined GRU with tf32 MMA ----------------
// grid (ceil(NN/64), 2). Block 512 = 16 warps: 4 M x 4 N. Tile m64 x n64, warp m16 x n16.
// Double-buffered dynamic smem per buffer: sAg[64][36] | sH[64][36] | sW[6*64][36].
// Weights stream via cp.async (already tf32/k-permuted in gmem); A/H staged via regs (cvt needed).
#define AH_WORDS (64 * 36)                       // 2304
#define W_WORDS  (6 * 64 * 36)                   // 13824
#define BUF_WORDS (2 * AH_WORDS + W_WORDS)       // 18432
#define GRU_SMEM_BYTES (2 * BUF_WORDS * 4)       // 147456

__global__ __launch_bounds__(512, 1) void gru_tf32_kernel(
    const float* __restrict__ agg, const float* __restrict__ h,
    const uint32_t* __restrict__ wtf,   // [6][128][128] tf32, k-permuted, this layer
    const float* __restrict__ b_ih, const float* __restrict__ b_hh,
    float* __restrict__ hnew)
{
    extern __shared__ uint32_t smem[];

    const int tid   = threadIdx.x;
    const int lane  = tid & 31;
    const int warp  = tid >> 5;
    const int wm    = warp & 3;
    const int wn    = warp >> 2;
    const int ty    = lane >> 2;
    const int tx    = lane & 3;
    const int node0 = blockIdx.x * 64;
    const int colB  = blockIdx.y * 64;

    // per-thread A/H staging assignment
    const int row_ld = tid >> 3;                 // 0..63
    const int k4_ld  = tid & 7;
    const int perm0  = (k4_ld >> 1) * 8 + (k4_ld & 1);
    int rr = node0 + row_ld; if (rr >= NN) rr = NN - 1;
    const float* aggp = agg + (size_t)rr * HID + k4_ld * 4;
    const float* hp_  = h   + (size_t)rr * HID + k4_ld * 4;

    float c[6][2][4];
#pragma unroll
    for (int g = 0; g < 6; g++)
#pragma unroll
        for (int t = 0; t < 2; t++)
#pragma unroll
            for (int i = 0; i < 4; i++) c[g][t][i] = 0.f;

    // buffer accessors
    auto AGb = [&](int b) { return (uint32_t(*)[36])(smem + b * BUF_WORDS); };
    auto Hb  = [&](int b) { return (uint32_t(*)[36])(smem + b * BUF_WORDS + AH_WORDS); };
    auto Wb  = [&](int b) { return (uint32_t(*)[36])(smem + b * BUF_WORDS + 2 * AH_WORDS); };

    // issue cp.async for weights chunk `kc` into buffer b
    auto load_w = [&](int kc, int b) {
        uint32_t (*sw)[36] = Wb(b);
#pragma unroll
        for (int r = 0; r < 6; r++) {
            int id  = tid + r * 512;
            int g   = id >> 9;
            int rem = id & 511;
            int n   = rem >> 3;
            int k4  = rem & 7;
            cp_async16(&sw[g * 64 + n][k4 * 4],
                       wtf + ((size_t)(g * HID + colB + n)) * HID + kc + k4 * 4);
        }
        cp_async_commit();
    };
    // cvt + STS staged A/H registers into buffer b
    auto sts_ah = [&](int b, float4 va, float4 vh) {
        uint32_t (*sag)[36] = AGb(b);
        uint32_t (*sh)[36]  = Hb(b);
        sag[row_ld][perm0 + 0] = f2tf(va.x);
        sag[row_ld][perm0 + 2] = f2tf(va.y);
        sag[row_ld][perm0 + 4] = f2tf(va.z);
        sag[row_ld][perm0 + 6] = f2tf(va.w);
        sh[row_ld][perm0 + 0] = f2tf(vh.x);
        sh[row_ld][perm0 + 2] = f2tf(vh.y);
        sh[row_ld][perm0 + 4] = f2tf(vh.z);
        sh[row_ld][perm0 + 6] = f2tf(vh.w);
    };
    // MMA over one chunk in buffer b
    auto do_mma = [&](int b) {
        uint32_t (*sag)[36] = AGb(b);
        uint32_t (*sh)[36]  = Hb(b);
        uint32_t (*sw)[36]  = Wb(b);
#pragma unroll
        for (int k8 = 0; k8 < 32; k8 += 8) {
            uint2 ag02 = *(const uint2*)&sag[wm * 16 + ty][k8 + 2 * tx];
            uint2 ag13 = *(const uint2*)&sag[wm * 16 + ty + 8][k8 + 2 * tx];
            uint2 h02  = *(const uint2*)&sh[wm * 16 + ty][k8 + 2 * tx];
            uint2 h13  = *(const uint2*)&sh[wm * 16 + ty + 8][k8 + 2 * tx];
#pragma unroll
            for (int t = 0; t < 2; t++) {
                int n = wn * 16 + t * 8 + ty;
#pragma unroll
                for (int g = 0; g < 3; g++) {
                    uint2 b2 = *(const uint2*)&sw[g * 64 + n][k8 + 2 * tx];
                    mma_tf32(c[g][t], ag02.x, ag13.x, ag02.y, ag13.y, b2.x, b2.y);
                }
#pragma unroll
                for (int g = 3; g < 6; g++) {
                    uint2 b2 = *(const uint2*)&sw[g * 64 + n][k8 + 2 * tx];
                    mma_tf32(c[g][t], h02.x, h13.x, h02.y, h13.y, b2.x, b2.y);
                }
            }
        }
    };

    // ---- prologue: chunk0 resident, chunk1 staged in regs ----
    float4 va = *(const float4*)(aggp + 0);
    float4 vh = *(const float4*)(hp_ + 0);
    load_w(0, 0);
    sts_ah(0, va, vh);
    va = *(const float4*)(aggp + 32);
    vh = *(const float4*)(hp_ + 32);
    cp_async_wait0();
    __syncthreads();

    // ---- pipelined main loop over 4 chunks ----
#pragma unroll
    for (int cchunk = 0; cchunk < 4; cchunk++) {
        int nb = (cchunk + 1) & 1;
        if (cchunk < 3) {
            load_w((cchunk + 1) * 32, nb);   // async, overlaps MMA
            sts_ah(nb, va, vh);              // regs hold chunk c+1
            if (cchunk < 2) {                // prefetch chunk c+2 into regs
                va = *(const float4*)(aggp + (cchunk + 2) * 32);
                vh = *(const float4*)(hp_ + (cchunk + 2) * 32);
            }
        }
        do_mma(cchunk & 1);
        if (cchunk < 3) {
            cp_async_wait0();
            __syncthreads();
        }
    }

    // ---- epilogue: gates + h_new ----
    const int r0 = node0 + wm * 16 + ty;
    const int r1 = r0 + 8;
#pragma unroll
    for (int t = 0; t < 2; t++) {
        int j = colB + wn * 16 + t * 8 + 2 * tx;
        float bir0 = b_ih[j],           bir1 = b_ih[j + 1];
        float biz0 = b_ih[HID + j],     biz1 = b_ih[HID + j + 1];
        float bin0 = b_ih[2 * HID + j], bin1 = b_ih[2 * HID + j + 1];
        float bhr0 = b_hh[j],           bhr1 = b_hh[j + 1];
        float bhz0 = b_hh[HID + j],     bhz1 = b_hh[HID + j + 1];
        float bhn0 = b_hh[2 * HID + j], bhn1 = b_hh[2 * HID + j + 1];

        if (r0 < NN) {
            float2 hp = *(const float2*)(h + (size_t)r0 * HID + j);
            float rr0 = sigmoidf_(c[0][t][0] + bir0 + c[3][t][0] + bhr0);
            float zz0 = sigmoidf_(c[1][t][0] + biz0 + c[4][t][0] + bhz0);
            float nn0 = tanhf(c[2][t][0] + bin0 + rr0 * (c[5][t][0] + bhn0));
            float rr1 = sigmoidf_(c[0][t][1] + bir1 + c[3][t][1] + bhr1);
            float zz1 = sigmoidf_(c[1][t][1] + biz1 + c[4][t][1] + bhz1);
            float nn1 = tanhf(c[2][t][1] + bin1 + rr1 * (c[5][t][1] + bhn1));
            *(float2*)&hnew[(size_t)r0 * HID + j] =
                make_float2((1.f - zz0) * nn0 + zz0 * hp.x,
                            (1.f - zz1) * nn1 + zz1 * hp.y);
        }
        if (r1 < NN) {
            float2 hp = *(const float2*)(h + (size_t)r1 * HID + j);
            float rr0 = sigmoidf_(c[0][t][2] + bir0 + c[3][t][2] + bhr0);
            float zz0 = sigmoidf_(c[1][t][2] + biz0 + c[4][t][2] + bhz0);
            float nn0 = tanhf(c[2][t][2] + bin0 + rr0 * (c[5][t][2] + bhn0));
            float rr1 = sigmoidf_(c[0][t][3] + bir1 + c[3][t][3] + bhr1);
            float zz1 = sigmoidf_(c[1][t][3] + biz1 + c[4][t][3] + bhz1);
            float nn1 = tanhf(c[2][t][3] + bin1 + rr1 * (c[5][t][3] + bhn1));
            *(float2*)&hnew[(size_t)r1 * HID + j] =
                make_float2((1.f - zz0) * nn0 + zz0 * hp.x,
                            (1.f - zz1) * nn1 + zz1 * hp.y);
        }
    }
}

// ---------------- relu -> out proj (128->40) -> log_softmax ----------------
__global__ __launch_bounds__(128) void out_kernel(
    const float* __restrict__ h, const float* __restrict__ W_out,
    const float* __restrict__ b_out, float* __restrict__ out)
{
    __shared__ float sW[128][48];
    __shared__ float sB[48];
    __shared__ float sH[4][128];

    const int tid = threadIdx.x;
    for (int i = tid; i < 128 * 48; i += 128) {
        int k = i / 48, cc = i % 48;
        sW[k][cc] = (cc < OUTC) ? W_out[(size_t)k * OUTC + cc] : 0.f;
    }
    if (tid < 48) sB[tid] = (tid < OUTC) ? b_out[tid] : 0.f;

    const int w = tid >> 5, lane = tid & 31;
    const int node = blockIdx.x * 4 + w;
    float4 hv = *(const float4*)(h + (size_t)node * HID + lane * 4);
    hv.x = fmaxf(hv.x, 0.f); hv.y = fmaxf(hv.y, 0.f);
    hv.z = fmaxf(hv.z, 0.f); hv.w = fmaxf(hv.w, 0.f);
    *(float4*)&sH[w][lane * 4] = hv;
    __syncthreads();

    const int c1 = 32 + (lane & 7);
    float acc0 = 0.f, acc1 = 0.f;
#pragma unroll 4
    for (int k = 0; k < 128; k++) {
        float a = sH[w][k];
        acc0 += a * sW[k][lane];
        acc1 += a * sW[k][c1];
    }
    float v0 = acc0 + sB[lane];
    float v1 = acc1 + sB[c1];
    const bool has1 = lane < 8;

    float mx = fmaxf(v0, has1 ? v1 : -INFINITY);
#pragma unroll
    for (int o = 16; o > 0; o >>= 1) mx = fmaxf(mx, __shfl_xor_sync(0xFFFFFFFFu, mx, o));
    float s = expf(v0 - mx) + (has1 ? expf(v1 - mx) : 0.f);
#pragma unroll
    for (int o = 16; o > 0; o >>= 1) s += __shfl_xor_sync(0xFFFFFFFFu, s, o);
    float lse = mx + logf(s);

    out[(size_t)node * OUTC + lane] = v0 - lse;
    if (has1) out[(size_t)node * OUTC + 32 + lane] = v1 - lse;
}

// ---------------- launch ----------------
extern "C" void kernel_launch(void* const* d_in, const int* in_sizes, int n_in,
                              void* d_out, int out_size)
{
    const float* x       = (const float*)d_in[0];
    const int*   ei      = (const int*)  d_in[1];
    const float* W_in    = (const float*)d_in[2];
    const float* b_in    = (const float*)d_in[3];
    const float* layer_W = (const float*)d_in[4];
    const float* W_ih    = (const float*)d_in[5];
    const float* W_hh    = (const float*)d_in[6];
    const float* b_ih    = (const float*)d_in[7];
    const float* b_hh    = (const float*)d_in[8];
    const float* W_out   = (const float*)d_in[9];
    const float* b_out   = (const float*)d_in[10];

    float *hbuf, *aggbuf, *hnewbuf, *wcbuf;
    uint32_t* wtfbuf;
    cudaGetSymbolAddress((void**)&hbuf,    g_h);
    cudaGetSymbolAddress((void**)&aggbuf,  g_agg);
    cudaGetSymbolAddress((void**)&hnewbuf, g_hnew);
    cudaGetSymbolAddress((void**)&wcbuf,   g_Wc);
    cudaGetSymbolAddress((void**)&wtfbuf,  g_Wtf);

    // opt-in to >48KB dynamic smem for the GRU kernel (host-side, immediate; capture-legal)
    cudaFuncSetAttribute(gru_tf32_kernel,
                         cudaFuncAttributeMaxDynamicSharedMemorySize, GRU_SMEM_BYTES);

    const int mmBlocks = (NN + 63) / 64;   // 782
    const int n4 = NN * HID / 4;           // 1.6M

    // precompute combined message+input-gate weights, then tf32-pack all GRU weights
    combine_kernel<<<dim3(12, 4, 3), 256>>>(layer_W, W_ih, wcbuf);
    pack_weights_kernel<<<3 * 6 * HID, 128>>>(wcbuf, W_hh, wtfbuf);

    gemm_tf32_kernel<<<mmBlocks, 256>>>(x, W_in, b_in, hbuf);

    float* hcur = hbuf;
    float* hnext = hnewbuf;
    for (int L = 0; L < 3; L++) {
        zero_kernel<<<(n4 + 255) / 256, 256>>>((float4*)aggbuf, n4);
        scatter_kernel<<<NE / 8, 256>>>(ei, hcur, aggbuf);
        gru_tf32_kernel<<<dim3(mmBlocks, 2), 512, GRU_SMEM_BYTES>>>(
            aggbuf, hcur, wtfbuf + (size_t)L * 6 * HID * HID, b_ih, b_hh, hnext);
        float* t = hcur; hcur = hnext; hnext = t;
    }

    out_kernel<<<NN / 4, 128>>>(hcur, W_out, b_out, (float*)d_out);
}

// round 17
// speedup vs baseline: 1.2025x; 1.1765x over previous
#include <cuda_runtime.h>
#include <cuda_bf16.h>
#include <math.h>
#include <stdint.h>

#define NN 50000
#define NE 800000
#define HID 128
#define OUTC 40

// ---------------- scratch (no allocation allowed; 256B-aligned) ----------------
__device__ __align__(256) float g_h[(size_t)NN * HID];
__device__ __align__(256) float g_hnew[(size_t)NN * HID];
__device__ __align__(256) float g_agg[(size_t)NN * HID];
__device__ __align__(256) float g_Wc[3 * 3 * HID * HID];
__device__ __align__(256) uint32_t g_Wtf[3 * 6 * HID * HID];
__device__ __align__(256) int g_cnt[NN];        // per-node in-degree
__device__ __align__(256) int g_offs[NN + 1];   // CSR offsets
__device__ __align__(256) int g_cursor[NN];     // fill cursors
__device__ __align__(256) int g_csr[NE];        // src ids sorted by dst

// ---------------- helpers ----------------
__device__ __forceinline__ uint32_t f2tf(float f)
{
    uint32_t r;
    asm("cvt.rna.tf32.f32 %0, %1;" : "=r"(r) : "f"(f));
    return r;
}

__device__ __forceinline__ void mma_tf32(float c[4],
    uint32_t a0, uint32_t a1, uint32_t a2, uint32_t a3,
    uint32_t b0, uint32_t b1)
{
    asm("mma.sync.aligned.m16n8k8.row.col.f32.tf32.tf32.f32 "
        "{%0,%1,%2,%3}, {%4,%5,%6,%7}, {%8,%9}, {%0,%1,%2,%3};"
        : "+f"(c[0]), "+f"(c[1]), "+f"(c[2]), "+f"(c[3])
        : "r"(a0), "r"(a1), "r"(a2), "r"(a3), "r"(b0), "r"(b1));
}

__device__ __forceinline__ void cp_async16(void* smem_dst, const void* gmem_src)
{
    unsigned sa = (unsigned)__cvta_generic_to_shared(smem_dst);
    asm volatile("cp.async.cg.shared.global [%0], [%1], 16;" :: "r"(sa), "l"(gmem_src));
}
__device__ __forceinline__ void cp_async_commit() { asm volatile("cp.async.commit_group;"); }
__device__ __forceinline__ void cp_async_wait0()  { asm volatile("cp.async.wait_group 0;"); }

__device__ __forceinline__ float sigmoidf_(float x) { return 1.f / (1.f + expf(-x)); }

// ---------------- combine: Wc_L[j][k'] = sum_c layer_W[L][k'][c] * W_ih[j][c] ----------------
__global__ __launch_bounds__(256) void combine_kernel(
    const float* __restrict__ layer_W, const float* __restrict__ W_ih,
    float* __restrict__ Wc)
{
    __shared__ float sWih[32][132];
    __shared__ float sW[32][132];

    const int L   = blockIdx.z;
    const int j0  = blockIdx.x * 32;
    const int kp0 = blockIdx.y * 32;
    const float* Wl = layer_W + (size_t)L * HID * HID;

    for (int i = threadIdx.x; i < 32 * 128; i += 256) {
        int row = i >> 7;
        int cc  = i & 127;
        sWih[row][cc] = W_ih[(size_t)(j0 + row) * HID + cc];
        sW[row][cc]   = Wl[(size_t)(kp0 + row) * HID + cc];
    }
    __syncthreads();

    const int j  = threadIdx.x & 31;
    const int kp = (threadIdx.x >> 5) * 4;
    float acc[4] = {0.f, 0.f, 0.f, 0.f};
#pragma unroll 4
    for (int c = 0; c < 128; c++) {
        float wij = sWih[j][c];
        acc[0] += wij * sW[kp + 0][c];
        acc[1] += wij * sW[kp + 1][c];
        acc[2] += wij * sW[kp + 2][c];
        acc[3] += wij * sW[kp + 3][c];
    }
    float* outp = Wc + (size_t)L * 3 * HID * HID + (size_t)(j0 + j) * HID + kp0 + kp;
    outp[0] = acc[0]; outp[1] = acc[1]; outp[2] = acc[2]; outp[3] = acc[3];
}

// ---------------- pack GRU weights to tf32 in k-permuted layout ----------------
__global__ __launch_bounds__(128) void pack_weights_kernel(
    const float* __restrict__ Wc, const float* __restrict__ W_hh,
    uint32_t* __restrict__ wtf)
{
    const int bid = blockIdx.x;
    const int L   = bid / 768;
    const int rem = bid % 768;
    const int g   = rem / 128;
    const int n   = rem % 128;

    const float* src = (g < 3)
        ? Wc + (size_t)L * 3 * HID * HID + (size_t)(g * HID + n) * HID
        : W_hh + (size_t)((g - 3) * HID + n) * HID;

    const int t = threadIdx.x;
    const int p = t & 7;
    const int src_k = (t & ~7) + (p >> 1) + 4 * (p & 1);
    wtf[(size_t)bid * HID + t] = f2tf(src[src_k]);
}

// ---------------- CSR build: zero counts, histogram, scan, fill ----------------
__global__ void zero_cnt_kernel(int* __restrict__ cnt)
{
    int i = blockIdx.x * blockDim.x + threadIdx.x;
    if (i < NN) cnt[i] = 0;
}

__global__ __launch_bounds__(256) void hist_kernel(const int* __restrict__ ei, int* __restrict__ cnt)
{
    int e = blockIdx.x * blockDim.x + threadIdx.x;
    if (e < NE) atomicAdd(&cnt[__ldg(ei + NE + e)], 1);
}

// single block, 1024 threads: offs = exclusive-scan shifted, cursor = start offsets
__global__ __launch_bounds__(1024) void scan_kernel(
    const int* __restrict__ cnt, int* __restrict__ offs, int* __restrict__ cursor)
{
    __shared__ int warpsum[32];
    __shared__ int s_running;
    const int tid  = threadIdx.x;
    const int lane = tid & 31;
    const int w    = tid >> 5;

    if (tid == 0) { s_running = 0; offs[0] = 0; }
    __syncthreads();

    for (int base = 0; base < NN; base += 1024) {
        int idx = base + tid;
        int c = (idx < NN) ? cnt[idx] : 0;
        // inclusive warp scan
        int x = c;
#pragma unroll
        for (int o = 1; o < 32; o <<= 1) {
            int y = __shfl_up_sync(0xFFFFFFFFu, x, o);
            if (lane >= o) x += y;
        }
        if (lane == 31) warpsum[w] = x;
        __syncthreads();
        if (w == 0) {
            int y = warpsum[lane];
#pragma unroll
            for (int o = 1; o < 32; o <<= 1) {
                int z = __shfl_up_sync(0xFFFFFFFFu, y, o);
                if (lane >= o) y += z;
            }
            warpsum[lane] = y;
        }
        __syncthreads();
        int incl = x + (w > 0 ? warpsum[w - 1] : 0);
        int run  = s_running;
        if (idx < NN) {
            offs[idx + 1] = run + incl;
            cursor[idx]   = run + incl - c;
        }
        __syncthreads();
        if (tid == 1023) s_running = run + incl;
        __syncthreads();
    }
}

__global__ __launch_bounds__(256) void fill_kernel(
    const int* __restrict__ ei, int* __restrict__ cursor, int* __restrict__ csr)
{
    int e = blockIdx.x * blockDim.x + threadIdx.x;
    if (e < NE) {
        int src = __ldg(ei + e);
        int dst = __ldg(ei + NE + e);
        int pos = atomicAdd(&cursor[dst], 1);
        csr[pos] = src;
    }
}

// ---------------- aggregate: warp per node, CSR gather-reduce (no atomics, no zeroing) ----------------
__global__ __launch_bounds__(256) void agg_kernel(
    const int* __restrict__ offs, const int* __restrict__ csr,
    const float* __restrict__ h, float* __restrict__ agg)
{
    const int node = blockIdx.x * 8 + (threadIdx.x >> 5);
    const int lane = threadIdx.x & 31;
    if (node >= NN) return;

    const int s = __ldg(offs + node);
    const int e = __ldg(offs + node + 1);

    float4 a0 = make_float4(0.f, 0.f, 0.f, 0.f);
    float4 a1 = make_float4(0.f, 0.f, 0.f, 0.f);
    int j = s;
    for (; j + 1 < e; j += 2) {
        int s0 = __ldg(csr + j);
        int s1 = __ldg(csr + j + 1);
        float4 v0 = *(const float4*)(h + (size_t)s0 * HID + lane * 4);
        float4 v1 = *(const float4*)(h + (size_t)s1 * HID + lane * 4);
        a0.x += v0.x; a0.y += v0.y; a0.z += v0.z; a0.w += v0.w;
        a1.x += v1.x; a1.y += v1.y; a1.z += v1.z; a1.w += v1.w;
    }
    if (j < e) {
        int s0 = __ldg(csr + j);
        float4 v0 = *(const float4*)(h + (size_t)s0 * HID + lane * 4);
        a0.x += v0.x; a0.y += v0.y; a0.z += v0.z; a0.w += v0.w;
    }
    a0.x += a1.x; a0.y += a1.y; a0.z += a1.z; a0.w += a1.w;
    *(float4*)(agg + (size_t)node * HID + lane * 4) = a0;
}

// ---------------- C[M,128] = A[M,128] @ W[128,128] (+bias), tf32 MMA ----------------
__global__ __launch_bounds__(256, 2) void gemm_tf32_kernel(
    const float* __restrict__ A, const float* __restrict__ W,
    const float* __restrict__ bias, float* __restrict__ C)
{
    __shared__ uint32_t sA[64][36];
    __shared__ uint32_t sB[128][36];

    const int tid  = threadIdx.x;
    const int lane = tid & 31;
    const int warp = tid >> 5;
    const int wm   = warp & 3;
    const int wn   = warp >> 2;
    const int ty   = lane >> 2;
    const int tx   = lane & 3;
    const int row0 = blockIdx.x * 64;

    float c[8][4];
#pragma unroll
    for (int t = 0; t < 8; t++)
#pragma unroll
        for (int i = 0; i < 4; i++) c[t][i] = 0.f;

    for (int kc = 0; kc < 128; kc += 32) {
#pragma unroll
        for (int r = 0; r < 2; r++) {
            int id  = tid + r * 256;
            int row = id >> 3;
            int k4  = id & 7;
            int rr  = row0 + row; if (rr >= NN) rr = NN - 1;
            float4 v = *(const float4*)(A + (size_t)rr * HID + kc + k4 * 4);
            int base = (k4 >> 1) * 8 + (k4 & 1);
            sA[row][base + 0] = f2tf(v.x);
            sA[row][base + 2] = f2tf(v.y);
            sA[row][base + 4] = f2tf(v.z);
            sA[row][base + 6] = f2tf(v.w);
        }
#pragma unroll
        for (int r = 0; r < 4; r++) {
            int id = tid + r * 256;
            int kk = id & 31;
            int nq = id >> 5;
            float4 v = *(const float4*)(W + (size_t)(kc + kk) * HID + nq * 4);
            int k8   = (kk >> 3) * 8;
            int phys = k8 + 2 * ((kk & 7) & 3) + ((kk & 7) >> 2);
            sB[nq * 4 + 0][phys] = f2tf(v.x);
            sB[nq * 4 + 1][phys] = f2tf(v.y);
            sB[nq * 4 + 2][phys] = f2tf(v.z);
            sB[nq * 4 + 3][phys] = f2tf(v.w);
        }
        __syncthreads();

#pragma unroll
        for (int k8 = 0; k8 < 32; k8 += 8) {
            uint2 a02 = *(const uint2*)&sA[wm * 16 + ty][k8 + 2 * tx];
            uint2 a13 = *(const uint2*)&sA[wm * 16 + ty + 8][k8 + 2 * tx];
#pragma unroll
            for (int t = 0; t < 8; t++) {
                int n = wn * 64 + t * 8 + ty;
                uint2 b = *(const uint2*)&sB[n][k8 + 2 * tx];
                mma_tf32(c[t], a02.x, a13.x, a02.y, a13.y, b.x, b.y);
            }
        }
        __syncthreads();
    }

    const int r0 = row0 + wm * 16 + ty;
    const int r1 = r0 + 8;
#pragma unroll
    for (int t = 0; t < 8; t++) {
        int col = wn * 64 + t * 8 + 2 * tx;
        float b0 = bias ? bias[col]     : 0.f;
        float b1 = bias ? bias[col + 1] : 0.f;
        if (r0 < NN)
            *(float2*)&C[(size_t)r0 * HID + col] = make_float2(c[t][0] + b0, c[t][1] + b1);
        if (r1 < NN)
            *(float2*)&C[(size_t)r1 * HID + col] = make_float2(c[t][2] + b0, c[t][3] + b1);
    }
}

// ---------------- pipelined GRU with tf32 MMA ----------------
#define AH_WORDS (64 * 36)
#define W_WORDS  (6 * 64 * 36)
#define BUF_WORDS (2 * AH_WORDS + W_WORDS)
#define GRU_SMEM_BYTES (2 * BUF_WORDS * 4)

__global__ __launch_bounds__(512, 1) void gru_tf32_kernel(
    const float* __restrict__ agg, const float* __restrict__ h,
    const uint32_t* __restrict__ wtf,
    const float* __restrict__ b_ih, const float* __restrict__ b_hh,
    float* __restrict__ hnew)
{
    extern __shared__ uint32_t smem[];

    const int tid   = threadIdx.x;
    const int lane  = tid & 31;
    const int warp  = tid >> 5;
    const int wm    = warp & 3;
    const int wn    = warp >> 2;
    const int ty    = lane >> 2;
    const int tx    = lane & 3;
    const int node0 = blockIdx.x * 64;
    const int colB  = blockIdx.y * 64;

    const int row_ld = tid >> 3;
    const int k4_ld  = tid & 7;
    const int perm0  = (k4_ld >> 1) * 8 + (k4_ld & 1);
    int rr = node0 + row_ld; if (rr >= NN) rr = NN - 1;
    const float* aggp = agg + (size_t)rr * HID + k4_ld * 4;
    const float* hp_  = h   + (size_t)rr * HID + k4_ld * 4;

    float c[6][2][4];
#pragma unroll
    for (int g = 0; g < 6; g++)
#pragma unroll
        for (int t = 0; t < 2; t++)
#pragma unroll
            for (int i = 0; i < 4; i++) c[g][t][i] = 0.f;

    auto AGb = [&](int b) { return (uint32_t(*)[36])(smem + b * BUF_WORDS); };
    auto Hb  = [&](int b) { return (uint32_t(*)[36])(smem + b * BUF_WORDS + AH_WORDS); };
    auto Wb  = [&](int b) { return (uint32_t(*)[36])(smem + b * BUF_WORDS + 2 * AH_WORDS); };

    auto load_w = [&](int kc, int b) {
        uint32_t (*sw)[36] = Wb(b);
#pragma unroll
        for (int r = 0; r < 6; r++) {
            int id  = tid + r * 512;
            int g   = id >> 9;
            int rem = id & 511;
            int n   = rem >> 3;
            int k4  = rem & 7;
            cp_async16(&sw[g * 64 + n][k4 * 4],
                       wtf + ((size_t)(g * HID + colB + n)) * HID + kc + k4 * 4);
        }
        cp_async_commit();
    };
    auto sts_ah = [&](int b, float4 va, float4 vh) {
        uint32_t (*sag)[36] = AGb(b);
        uint32_t (*sh)[36]  = Hb(b);
        sag[row_ld][perm0 + 0] = f2tf(va.x);
        sag[row_ld][perm0 + 2] = f2tf(va.y);
        sag[row_ld][perm0 + 4] = f2tf(va.z);
        sag[row_ld][perm0 + 6] = f2tf(va.w);
        sh[row_ld][perm0 + 0] = f2tf(vh.x);
        sh[row_ld][perm0 + 2] = f2tf(vh.y);
        sh[row_ld][perm0 + 4] = f2tf(vh.z);
        sh[row_ld][perm0 + 6] = f2tf(vh.w);
    };
    auto do_mma = [&](int b) {
        uint32_t (*sag)[36] = AGb(b);
        uint32_t (*sh)[36]  = Hb(b);
        uint32_t (*sw)[36]  = Wb(b);
#pragma unroll
        for (int k8 = 0; k8 < 32; k8 += 8) {
            uint2 ag02 = *(const uint2*)&sag[wm * 16 + ty][k8 + 2 * tx];
            uint2 ag13 = *(const uint2*)&sag[wm * 16 + ty + 8][k8 + 2 * tx];
            uint2 h02  = *(const uint2*)&sh[wm * 16 + ty][k8 + 2 * tx];
            uint2 h13  = *(const uint2*)&sh[wm * 16 + ty + 8][k8 + 2 * tx];
#pragma unroll
            for (int t = 0; t < 2; t++) {
                int n = wn * 16 + t * 8 + ty;
#pragma unroll
                for (int g = 0; g < 3; g++) {
                    uint2 b2 = *(const uint2*)&sw[g * 64 + n][k8 + 2 * tx];
                    mma_tf32(c[g][t], ag02.x, ag13.x, ag02.y, ag13.y, b2.x, b2.y);
                }
#pragma unroll
                for (int g = 3; g < 6; g++) {
                    uint2 b2 = *(const uint2*)&sw[g * 64 + n][k8 + 2 * tx];
                    mma_tf32(c[g][t], h02.x, h13.x, h02.y, h13.y, b2.x, b2.y);
                }
            }
        }
    };

    float4 va = *(const float4*)(aggp + 0);
    float4 vh = *(const float4*)(hp_ + 0);
    load_w(0, 0);
    sts_ah(0, va, vh);
    va = *(const float4*)(aggp + 32);
    vh = *(const float4*)(hp_ + 32);
    cp_async_wait0();
    __syncthreads();

#pragma unroll
    for (int cchunk = 0; cchunk < 4; cchunk++) {
        int nb = (cchunk + 1) & 1;
        if (cchunk < 3) {
            load_w((cchunk + 1) * 32, nb);
            sts_ah(nb, va, vh);
            if (cchunk < 2) {
                va = *(const float4*)(aggp + (cchunk + 2) * 32);
                vh = *(const float4*)(hp_ + (cchunk + 2) * 32);
            }
        }
        do_mma(cchunk & 1);
        if (cchunk < 3) {
            cp_async_wait0();
            __syncthreads();
        }
    }

    const int r0 = node0 + wm * 16 + ty;
    const int r1 = r0 + 8;
#pragma unroll
    for (int t = 0; t < 2; t++) {
        int j = colB + wn * 16 + t * 8 + 2 * tx;
        float bir0 = b_ih[j],           bir1 = b_ih[j + 1];
        float biz0 = b_ih[HID + j],     biz1 = b_ih[HID + j + 1];
        float bin0 = b_ih[2 * HID + j], bin1 = b_ih[2 * HID + j + 1];
        float bhr0 = b_hh[j],           bhr1 = b_hh[j + 1];
        float bhz0 = b_hh[HID + j],     bhz1 = b_hh[HID + j + 1];
        float bhn0 = b_hh[2 * HID + j], bhn1 = b_hh[2 * HID + j + 1];

        if (r0 < NN) {
            float2 hp = *(const float2*)(h + (size_t)r0 * HID + j);
            float rr0 = sigmoidf_(c[0][t][0] + bir0 + c[3][t][0] + bhr0);
            float zz0 = sigmoidf_(c[1][t][0] + biz0 + c[4][t][0] + bhz0);
            float nn0 = tanhf(c[2][t][0] + bin0 + rr0 * (c[5][t][0] + bhn0));
            float rr1 = sigmoidf_(c[0][t][1] + bir1 + c[3][t][1] + bhr1);
            float zz1 = sigmoidf_(c[1][t][1] + biz1 + c[4][t][1] + bhz1);
            float nn1 = tanhf(c[2][t][1] + bin1 + rr1 * (c[5][t][1] + bhn1));
            *(float2*)&hnew[(size_t)r0 * HID + j] =
                make_float2((1.f - zz0) * nn0 + zz0 * hp.x,
                            (1.f - zz1) * nn1 + zz1 * hp.y);
        }
        if (r1 < NN) {
            float2 hp = *(const float2*)(h + (size_t)r1 * HID + j);
            float rr0 = sigmoidf_(c[0][t][2] + bir0 + c[3][t][2] + bhr0);
            float zz0 = sigmoidf_(c[1][t][2] + biz0 + c[4][t][2] + bhz0);
            float nn0 = tanhf(c[2][t][2] + bin0 + rr0 * (c[5][t][2] + bhn0));
            float rr1 = sigmoidf_(c[0][t][3] + bir1 + c[3][t][3] + bhr1);
            float zz1 = sigmoidf_(c[1][t][3] + biz1 + c[4][t][3] + bhz1);
            float nn1 = tanhf(c[2][t][3] + bin1 + rr1 * (c[5][t][3] + bhn1));
            *(float2*)&hnew[(size_t)r1 * HID + j] =
                make_float2((1.f - zz0) * nn0 + zz0 * hp.x,
                            (1.f - zz1) * nn1 + zz1 * hp.y);
        }
    }
}

// ---------------- relu -> out proj (128->40) -> log_softmax ----------------
__global__ __launch_bounds__(128) void out_kernel(
    const float* __restrict__ h, const float* __restrict__ W_out,
    const float* __restrict__ b_out, float* __restrict__ out)
{
    __shared__ float sW[128][48];
    __shared__ float sB[48];
    __shared__ float sH[4][128];

    const int tid = threadIdx.x;
    for (int i = tid; i < 128 * 48; i += 128) {
        int k = i / 48, cc = i % 48;
        sW[k][cc] = (cc < OUTC) ? W_out[(size_t)k * OUTC + cc] : 0.f;
    }
    if (tid < 48) sB[tid] = (tid < OUTC) ? b_out[tid] : 0.f;

    const int w = tid >> 5, lane = tid & 31;
    const int node = blockIdx.x * 4 + w;
    float4 hv = *(const float4*)(h + (size_t)node * HID + lane * 4);
    hv.x = fmaxf(hv.x, 0.f); hv.y = fmaxf(hv.y, 0.f);
    hv.z = fmaxf(hv.z, 0.f); hv.w = fmaxf(hv.w, 0.f);
    *(float4*)&sH[w][lane * 4] = hv;
    __syncthreads();

    const int c1 = 32 + (lane & 7);
    float acc0 = 0.f, acc1 = 0.f;
#pragma unroll 4
    for (int k = 0; k < 128; k++) {
        float a = sH[w][k];
        acc0 += a * sW[k][lane];
        acc1 += a * sW[k][c1];
    }
    float v0 = acc0 + sB[lane];
    float v1 = acc1 + sB[c1];
    const bool has1 = lane < 8;

    float mx = fmaxf(v0, has1 ? v1 : -INFINITY);
#pragma unroll
    for (int o = 16; o > 0; o >>= 1) mx = fmaxf(mx, __shfl_xor_sync(0xFFFFFFFFu, mx, o));
    float s = expf(v0 - mx) + (has1 ? expf(v1 - mx) : 0.f);
#pragma unroll
    for (int o = 16; o > 0; o >>= 1) s += __shfl_xor_sync(0xFFFFFFFFu, s, o);
    float lse = mx + logf(s);

    out[(size_t)node * OUTC + lane] = v0 - lse;
    if (has1) out[(size_t)node * OUTC + 32 + lane] = v1 - lse;
}

// ---------------- launch ----------------
extern "C" void kernel_launch(void* const* d_in, const int* in_sizes, int n_in,
                              void* d_out, int out_size)
{
    const float* x       = (const float*)d_in[0];
    const int*   ei      = (const int*)  d_in[1];
    const float* W_in    = (const float*)d_in[2];
    const float* b_in    = (const float*)d_in[3];
    const float* layer_W = (const float*)d_in[4];
    const float* W_ih    = (const float*)d_in[5];
    const float* W_hh    = (const float*)d_in[6];
    const float* b_ih    = (const float*)d_in[7];
    const float* b_hh    = (const float*)d_in[8];
    const float* W_out   = (const float*)d_in[9];
    const float* b_out   = (const float*)d_in[10];

    float *hbuf, *aggbuf, *hnewbuf, *wcbuf;
    uint32_t* wtfbuf;
    int *cntbuf, *offsbuf, *curbuf, *csrbuf;
    cudaGetSymbolAddress((void**)&hbuf,    g_h);
    cudaGetSymbolAddress((void**)&aggbuf,  g_agg);
    cudaGetSymbolAddress((void**)&hnewbuf, g_hnew);
    cudaGetSymbolAddress((void**)&wcbuf,   g_Wc);
    cudaGetSymbolAddress((void**)&wtfbuf,  g_Wtf);
    cudaGetSymbolAddress((void**)&cntbuf,  g_cnt);
    cudaGetSymbolAddress((void**)&offsbuf, g_offs);
    cudaGetSymbolAddress((void**)&curbuf,  g_cursor);
    cudaGetSymbolAddress((void**)&csrbuf,  g_csr);

    cudaFuncSetAttribute(gru_tf32_kernel,
                         cudaFuncAttributeMaxDynamicSharedMemorySize, GRU_SMEM_BYTES);

    const int mmBlocks = (NN + 63) / 64;   // 782

    // weight prep
    combine_kernel<<<dim3(12, 4, 3), 256>>>(layer_W, W_ih, wcbuf);
    pack_weights_kernel<<<3 * 6 * HID, 128>>>(wcbuf, W_hh, wtfbuf);

    // CSR build (edge list constant across layers)
    zero_cnt_kernel<<<(NN + 255) / 256, 256>>>(cntbuf);
    hist_kernel<<<(NE + 255) / 256, 256>>>(ei, cntbuf);
    scan_kernel<<<1, 1024>>>(cntbuf, offsbuf, curbuf);
    fill_kernel<<<(NE + 255) / 256, 256>>>(ei, curbuf, csrbuf);

    gemm_tf32_kernel<<<mmBlocks, 256>>>(x, W_in, b_in, hbuf);

    float* hcur = hbuf;
    float* hnext = hnewbuf;
    for (int L = 0; L < 3; L++) {
        agg_kernel<<<(NN + 7) / 8, 256>>>(offsbuf, csrbuf, hcur, aggbuf);
        gru_tf32_kernel<<<dim3(mmBlocks, 2), 512, GRU_SMEM_BYTES>>>(
            aggbuf, hcur, wtfbuf + (size_t)L * 6 * HID * HID, b_ih, b_hh, hnext);
        float* t = hcur; hcur = hnext; hnext = t;
    }

    out_kernel<<<NN / 4, 128>>>(hcur, W_out, b_out, (float*)d_out);
}